// round 12
// baseline (speedup 1.0000x reference)
#include <cuda_runtime.h>
#include <cstdint>

// LanczosInterpolationLayer: x f32 [32,3,512,512] -> Lanczos4 2x upsample ->
// per-image range renormalize -> *255 -> uint8 (saturating trunc) -> f32 out.
//
// R8=189us best; R9/R11 showed pass-2 is issue-slot bound (83%). R12 cuts
// issue count structurally with packed f32x2 (FFMA2 via inline PTX):
//  - s_ut -> float2 row-pair layout (out rows 2m,2m+1 share H-pass windows
//    and weights exactly -> perfect SIMD2 lanes).
//  - stage B: two scalar STS fuse into one STS.64 per (pair,col).
//  - stage C: LDS.64 window loads (half the loads), 8x fma.rn.f32x2 per
//    pixel-PAIR (half the FMA issues). Per-lane IEEE == fmaf -> identical
//    numerics to R8/R11.

#define NIMG   32
#define NCH    96
#define IN_SZ  512
#define OUT_SZ 1024
#define TILE_W 64           // output cols per block
#define TILE_H 128          // output rows per block
#define PAT_W  40           // input patch cols (32 + 8 halo)
#define PAT_H  72           // input patch rows (64 + 8 halo)
#define PSTR   41           // s_in stride (odd -> conflict-free vertical)
#define UPSTR  41           // s_up stride in float2 pairs
#define SLOTS  128          // blocks per channel (16 x * 8 y)

typedef unsigned long long u64;

__device__ float g_pmin[NCH * SLOTS];
__device__ float g_pmax[NCH * SLOTS];

// Normalized Lanczos4 weights, even phase (output 2m): tap j hits input m-4+j.
#define WE0 (-0.0039706f)
#define WE1 ( 0.0314676f)
#define WE2 (-0.0916620f)
#define WE3 ( 0.2826868f)
#define WE4 ( 0.8933939f)
#define WE5 (-0.1523043f)
#define WE6 ( 0.0554435f)
#define WE7 (-0.0150549f)

// scalar filters (stage B)
#define EVEN8(a0,a1,a2,a3,a4,a5,a6,a7) \
  fmaf((a7), WE7, fmaf((a6), WE6, fmaf((a5), WE5, fmaf((a4), WE4, \
  fmaf((a3), WE3, fmaf((a2), WE2, fmaf((a1), WE1, (a0) * WE0)))))))
#define ODD8(a1,a2,a3,a4,a5,a6,a7,a8) \
  fmaf((a8), WE0, fmaf((a7), WE1, fmaf((a6), WE2, fmaf((a5), WE3, \
  fmaf((a4), WE4, fmaf((a3), WE5, fmaf((a2), WE6, (a1) * WE7)))))))

// ---- packed f32x2 primitives ----
static __device__ __forceinline__ u64 pk2(float lo, float hi) {
    u64 r; asm("mov.b64 %0,{%1,%2};" : "=l"(r) : "f"(lo), "f"(hi)); return r;
}
static __device__ __forceinline__ float2 upk2(u64 v) {
    float2 r; asm("mov.b64 {%0,%1},%2;" : "=f"(r.x), "=f"(r.y) : "l"(v)); return r;
}
static __device__ __forceinline__ u64 fma2_(u64 a, u64 b, u64 c) {
    u64 d; asm("fma.rn.f32x2 %0,%1,%2,%3;" : "=l"(d) : "l"(a), "l"(b), "l"(c)); return d;
}
static __device__ __forceinline__ u64 mul2_(u64 a, u64 b) {
    u64 d; asm("mul.rn.f32x2 %0,%1,%2;" : "=l"(d) : "l"(a), "l"(b)); return d;
}

// packed filters: W = broadcast weight pairs; same op order as scalar ones.
#define EVEN8P(W,a0,a1,a2,a3,a4,a5,a6,a7) \
  fma2_((a7), W[7], fma2_((a6), W[6], fma2_((a5), W[5], fma2_((a4), W[4], \
  fma2_((a3), W[3], fma2_((a2), W[2], fma2_((a1), W[1], mul2_((a0), W[0]))))))))
#define ODD8P(W,a1,a2,a3,a4,a5,a6,a7,a8) \
  fma2_((a8), W[0], fma2_((a7), W[1], fma2_((a6), W[2], fma2_((a5), W[3], \
  fma2_((a4), W[4], fma2_((a3), W[5], fma2_((a2), W[6], mul2_((a1), W[7]))))))))

// CVT-free floor for f in [0,~300): RN(f - 0.5-eps) via 1.5*2^23 magic add.
// Caller clamps the 255 mass point AFTER (R11-verified ordering).
static __device__ __forceinline__ float floor_pos(float f) {
    float t = (f - 0.49999997f) + 12582912.0f;
    return t - 12582912.0f;
}

static __device__ __forceinline__ float2 quant2(u64 v, u64 P1p, u64 P3p, u64 Q3p) {
    u64 a = mul2_(v, P1p);
    u64 b = fma2_(v, P3p, Q3p);
    float2 fa = upk2(a), fb = upk2(b);
    float x = fmaxf(fminf(fa.x, fb.x), 0.0f);
    float y = fmaxf(fminf(fa.y, fb.y), 0.0f);
    x = fminf(floor_pos(x), 255.0f);
    y = fminf(floor_pos(y), 255.0f);
    return make_float2(x, y);
}

template <bool WRITE>
__global__ void __launch_bounds__(256, 4)
k_resize(const float* __restrict__ x, float* __restrict__ out)
{
    __shared__ float  s_in[PAT_H * PSTR];   // input patch [irow][icol]
    __shared__ float2 s_up[64 * UPSTR];     // H-pass, row-PAIR major [m][icol]
    __shared__ float  s_red[16];

    const int tid = threadIdx.x;
    const int bc  = blockIdx.z;                  // image*3 + channel
    const int m0  = blockIdx.y * (TILE_H / 2);   // input row base
    const int n0  = blockIdx.x * (TILE_W / 2);   // input col base
    const float* src = x + (size_t)bc * (IN_SZ * IN_SZ);

    // broadcast weight pairs
    u64 WP[8];
    WP[0] = pk2(WE0, WE0); WP[1] = pk2(WE1, WE1);
    WP[2] = pk2(WE2, WE2); WP[3] = pk2(WE3, WE3);
    WP[4] = pk2(WE4, WE4); WP[5] = pk2(WE5, WE5);
    WP[6] = pk2(WE6, WE6); WP[7] = pk2(WE7, WE7);

    // ---- pass 2 only: reduce this image's 384 min/max partials ----
    if (WRITE) {
        const int img3 = (bc / 3) * 3;
        float a = __int_as_float(0x7f800000);
        float b = -a;
        #pragma unroll
        for (int i = 0; i < 2; i++) {
            int idx = tid + 256 * i;
            if (idx < 3 * SLOTS) {
                a = fminf(a, g_pmin[img3 * SLOTS + idx]);
                b = fmaxf(b, g_pmax[img3 * SLOTS + idx]);
            }
        }
        #pragma unroll
        for (int m = 16; m; m >>= 1) {
            a = fminf(a, __shfl_xor_sync(0xffffffffu, a, m));
            b = fmaxf(b, __shfl_xor_sync(0xffffffffu, b, m));
        }
        if ((tid & 31) == 0) {
            s_red[tid >> 5]       = a;
            s_red[8 + (tid >> 5)] = b;
        }
    }

    // ---- stage A: load input patch with replicate border ----
    #pragma unroll
    for (int i = 0; i < 12; i++) {
        int idx = tid + 256 * i;
        if (idx < PAT_H * PAT_W) {
            int r = idx / PAT_W;
            int c = idx - r * PAT_W;
            int gy = min(max(m0 - 4 + r, 0), IN_SZ - 1);
            int gx = min(max(n0 - 4 + c, 0), IN_SZ - 1);
            s_in[r * PSTR + c] = src[gy * IN_SZ + gx];
        }
    }
    __syncthreads();

    // renorm collapsed: f(v) = min(P1*v, P3*v + Q3), clamp0 -> floor -> min255
    u64 P1p = 0, P3p = 0, Q3p = 0;
    if (WRITE) {
        float mn = s_red[0], mx = s_red[8];
        #pragma unroll
        for (int i = 1; i < 8; i++) {
            mn = fminf(mn, s_red[i]);
            mx = fmaxf(mx, s_red[8 + i]);
        }
        float P1 = 255.f, P3 = 255.f, Q3 = 0.f;
        if ((mx - mn) > 1.0f) {
            const float ott = 1.0f / 255.0f;
            const float ubt = -10.0f / 255.0f;
            float otr = mx - 1.0f;
            float s1 = ott / (otr != 0.0f ? otr : 1.0f);
            float c1 = 1.0f - ott;
            float c2 = 1.0f - ubt;
            P1 = 255.0f * c1 * c2;
            P3 = 255.0f * s1 * c2;
            Q3 = 255.0f * c2 * (c1 - s1);
        }
        P1p = pk2(P1, P1); P3p = pk2(P3, P3); Q3p = pk2(Q3, Q3);
    }

    // ---- stage B: vertical resample -> s_up[pair m][icol] = (even,odd) ----
    for (int t = tid; t < PAT_W * 8; t += 256) {
        int g  = t / PAT_W;
        int ic = t - g * PAT_W;
        int mb = g * 8;
        const float* p = &s_in[mb * PSTR + ic];
        float w0 = p[0 * PSTR], w1 = p[1 * PSTR], w2 = p[2 * PSTR];
        float w3 = p[3 * PSTR], w4 = p[4 * PSTR], w5 = p[5 * PSTR];
        float w6 = p[6 * PSTR], w7 = p[7 * PSTR], w8 = p[8 * PSTR];
        #pragma unroll
        for (int mm = 0; mm < 8; mm++) {
            float e = EVEN8(w0, w1, w2, w3, w4, w5, w6, w7);
            float o = ODD8(w1, w2, w3, w4, w5, w6, w7, w8);
            s_up[(mb + mm) * UPSTR + ic] = make_float2(e, o);   // STS.64
            w0 = w1; w1 = w2; w2 = w3; w3 = w4;
            w4 = w5; w5 = w6; w6 = w7; w7 = w8;
            if (mm < 7) w8 = p[(mm + 9) * PSTR];
        }
    }
    __syncthreads();

    // ---- stage C: horizontal resample on row-pairs ----
    if (!WRITE) {
        // one task/thread: row-pair mp (0..63), 16-col quarter q (0..3)
        const int q  = tid & 3;
        const int mp = tid >> 2;
        const u64* wp = reinterpret_cast<const u64*>(&s_up[mp * UPSTR + 8 * q]);
        u64 w[16];
        #pragma unroll
        for (int j = 0; j < 16; j++) w[j] = wp[j];   // LDS.64

        float vmin = __int_as_float(0x7f800000);
        float vmax = -vmin;
        #pragma unroll
        for (int i = 0; i < 8; i++) {
            u64 e = EVEN8P(WP, w[i],     w[i + 1], w[i + 2], w[i + 3],
                               w[i + 4], w[i + 5], w[i + 6], w[i + 7]);
            u64 o = ODD8P (WP, w[i + 1], w[i + 2], w[i + 3], w[i + 4],
                               w[i + 5], w[i + 6], w[i + 7], w[i + 8]);
            float2 fe = upk2(e), fo = upk2(o);
            vmin = fminf(vmin, fminf(fminf(fe.x, fe.y), fminf(fo.x, fo.y)));
            vmax = fmaxf(vmax, fmaxf(fmaxf(fe.x, fe.y), fmaxf(fo.x, fo.y)));
        }
        #pragma unroll
        for (int m = 16; m; m >>= 1) {
            vmin = fminf(vmin, __shfl_xor_sync(0xffffffffu, vmin, m));
            vmax = fmaxf(vmax, __shfl_xor_sync(0xffffffffu, vmax, m));
        }
        int w5 = tid >> 5, l = tid & 31;
        if (l == 0) { s_red[w5] = vmin; s_red[8 + w5] = vmax; }
        __syncthreads();
        if (tid == 0) {
            float a = s_red[0], b = s_red[8];
            #pragma unroll
            for (int i = 1; i < 8; i++) {
                a = fminf(a, s_red[i]);
                b = fmaxf(b, s_red[8 + i]);
            }
            int slot = blockIdx.y * 16 + blockIdx.x;
            g_pmin[bc * SLOTS + slot] = a;
            g_pmax[bc * SLOTS + slot] = b;
        }
    } else {
        // thread = (row-pair group mq 0..15, 4-col segment seg 0..15)
        const int seg = tid & 15;
        const int mq  = tid >> 4;
        float* dbase = out + ((size_t)bc * OUT_SZ + blockIdx.y * TILE_H)
                           * OUT_SZ + blockIdx.x * TILE_W + seg * 4;
        #pragma unroll
        for (int it = 0; it < 4; it++) {
            const int p = it * 16 + mq;
            const u64* wp = reinterpret_cast<const u64*>(&s_up[p * UPSTR + 2 * seg]);
            u64 w0 = wp[0], w1 = wp[1], w2 = wp[2], w3 = wp[3], w4 = wp[4],
                w5 = wp[5], w6 = wp[6], w7 = wp[7], w8 = wp[8], w9 = wp[9];
            u64 q0 = EVEN8P(WP, w0, w1, w2, w3, w4, w5, w6, w7);
            u64 q1 = ODD8P (WP, w1, w2, w3, w4, w5, w6, w7, w8);
            u64 q2 = EVEN8P(WP, w1, w2, w3, w4, w5, w6, w7, w8);
            u64 q3 = ODD8P (WP, w2, w3, w4, w5, w6, w7, w8, w9);
            float2 r0 = quant2(q0, P1p, P3p, Q3p);
            float2 r1 = quant2(q1, P1p, P3p, Q3p);
            float2 r2 = quant2(q2, P1p, P3p, Q3p);
            float2 r3 = quant2(q3, P1p, P3p, Q3p);
            float* d0 = dbase + (size_t)(2 * p) * OUT_SZ;
            *reinterpret_cast<float4*>(d0) =
                make_float4(r0.x, r1.x, r2.x, r3.x);          // row 2p
            *reinterpret_cast<float4*>(d0 + OUT_SZ) =
                make_float4(r0.y, r1.y, r2.y, r3.y);          // row 2p+1
        }
    }
}

extern "C" void kernel_launch(void* const* d_in, const int* in_sizes, int n_in,
                              void* d_out, int out_size)
{
    const float* x = (const float*)d_in[0];
    float* out = (float*)d_out;

    dim3 grid(OUT_SZ / TILE_W, OUT_SZ / TILE_H, NCH);
    k_resize<false><<<grid, 256>>>(x, nullptr);
    k_resize<true ><<<grid, 256>>>(x, out);
}

// round 13
// speedup vs baseline: 1.1276x; 1.1276x over previous
#include <cuda_runtime.h>
#include <cstdint>

// LanczosInterpolationLayer: x f32 [32,3,512,512] -> Lanczos4 2x upsample ->
// per-image range renormalize -> *255 -> uint8 (saturating trunc) -> f32 out.
//
// R13 = exact R8 dataflow (best: 189us) + epilogue collapsed analytically:
//   P3/Q3 branch is dead (for v>1 both affine paths exceed 255 and clamp),
//   P1 = 255*c1*c2 is a data-independent constant; min/max only feed the
//   boolean doNorm = (mx-mn)>1.  Quantize = I2F(F2I_rz(min(P1*v, 255))).

#define NIMG   32
#define NCH    96
#define IN_SZ  512
#define OUT_SZ 1024
#define TILE_W 64           // output cols per block
#define TILE_H 128          // output rows per block
#define PAT_W  40           // input patch cols (32 + 8 halo)
#define PAT_H  72           // input patch rows (64 + 8 halo)
#define PSTR   41           // s_in stride (odd -> conflict-free)
#define USTR   41           // s_ut stride [orow][icol] (conflict-free)
#define SLOTS  128          // blocks per channel (16 x * 8 y)

__device__ float g_pmin[NCH * SLOTS];
__device__ float g_pmax[NCH * SLOTS];

// Normalized Lanczos4 weights, even phase (output 2m): tap j hits input m-4+j.
#define WE0 (-0.0039706f)
#define WE1 ( 0.0314676f)
#define WE2 (-0.0916620f)
#define WE3 ( 0.2826868f)
#define WE4 ( 0.8933939f)
#define WE5 (-0.1523043f)
#define WE6 ( 0.0554435f)
#define WE7 (-0.0150549f)

#define EVEN8(a0,a1,a2,a3,a4,a5,a6,a7) \
  fmaf((a7), WE7, fmaf((a6), WE6, fmaf((a5), WE5, fmaf((a4), WE4, \
  fmaf((a3), WE3, fmaf((a2), WE2, fmaf((a1), WE1, (a0) * WE0)))))))
#define ODD8(a1,a2,a3,a4,a5,a6,a7,a8) \
  fmaf((a8), WE0, fmaf((a7), WE1, fmaf((a6), WE2, fmaf((a5), WE3, \
  fmaf((a4), WE4, fmaf((a3), WE5, fmaf((a2), WE6, (a1) * WE7)))))))

template <bool WRITE>
__global__ void __launch_bounds__(256, 5)
k_resize(const float* __restrict__ x, float* __restrict__ out)
{
    __shared__ float s_in[PAT_H * PSTR];    // input patch  [irow][icol]
    __shared__ float s_ut[TILE_H * USTR];   // H-resampled  [orow][icol]
    __shared__ float s_red[16];

    const int tid = threadIdx.x;
    const int bc  = blockIdx.z;                  // image*3 + channel
    const int m0  = blockIdx.y * (TILE_H / 2);   // input row base
    const int n0  = blockIdx.x * (TILE_W / 2);   // input col base
    const float* src = x + (size_t)bc * (IN_SZ * IN_SZ);

    // ---- pass 2 only: reduce this image's 384 min/max partials ----
    if (WRITE) {
        const int img3 = (bc / 3) * 3;
        float a = __int_as_float(0x7f800000);
        float b = -a;
        #pragma unroll
        for (int i = 0; i < 2; i++) {
            int idx = tid + 256 * i;
            if (idx < 3 * SLOTS) {
                a = fminf(a, g_pmin[img3 * SLOTS + idx]);
                b = fmaxf(b, g_pmax[img3 * SLOTS + idx]);
            }
        }
        #pragma unroll
        for (int m = 16; m; m >>= 1) {
            a = fminf(a, __shfl_xor_sync(0xffffffffu, a, m));
            b = fmaxf(b, __shfl_xor_sync(0xffffffffu, b, m));
        }
        if ((tid & 31) == 0) {
            s_red[tid >> 5]       = a;
            s_red[8 + (tid >> 5)] = b;
        }
    }

    // ---- stage A: load input patch with replicate border ----
    #pragma unroll
    for (int i = 0; i < 12; i++) {
        int idx = tid + 256 * i;
        if (idx < PAT_H * PAT_W) {
            int r = idx / PAT_W;
            int c = idx - r * PAT_W;
            int gy = min(max(m0 - 4 + r, 0), IN_SZ - 1);
            int gx = min(max(n0 - 4 + c, 0), IN_SZ - 1);
            s_in[r * PSTR + c] = src[gy * IN_SZ + gx];
        }
    }
    __syncthreads();

    // epilogue constant: f = clamp(trunc(min(P1*v, 255)), 0, 255)
    //   doNorm: P1 = 255*c1*c2 (data-independent); else P1 = 255.
    float P1 = 255.0f;
    if (WRITE) {
        float mn = s_red[0], mx = s_red[8];
        #pragma unroll
        for (int i = 1; i < 8; i++) {
            mn = fminf(mn, s_red[i]);
            mx = fmaxf(mx, s_red[8 + i]);
        }
        if ((mx - mn) > 1.0f) {
            const float c1 = 1.0f - 1.0f / 255.0f;     // 254/255
            const float c2 = 1.0f + 10.0f / 255.0f;    // 265/255
            P1 = 255.0f * c1 * c2;                      // 263.9608
        }
    }

    // ---- stage B: vertical (height) resample -> s_ut[orow][icol] ----
    for (int t = tid; t < PAT_W * 8; t += 256) {
        int g  = t / PAT_W;
        int ic = t - g * PAT_W;
        int mb = g * 8;
        const float* p = &s_in[mb * PSTR + ic];
        float w0 = p[0 * PSTR], w1 = p[1 * PSTR], w2 = p[2 * PSTR];
        float w3 = p[3 * PSTR], w4 = p[4 * PSTR], w5 = p[5 * PSTR];
        float w6 = p[6 * PSTR], w7 = p[7 * PSTR], w8 = p[8 * PSTR];
        float* q = &s_ut[2 * mb * USTR + ic];
        #pragma unroll
        for (int mm = 0; mm < 8; mm++) {
            q[(2 * mm)     * USTR] = EVEN8(w0, w1, w2, w3, w4, w5, w6, w7);
            q[(2 * mm + 1) * USTR] = ODD8(w1, w2, w3, w4, w5, w6, w7, w8);
            w0 = w1; w1 = w2; w2 = w3; w3 = w4;
            w4 = w5; w5 = w6; w6 = w7; w7 = w8;
            if (mm < 7) w8 = p[(mm + 9) * PSTR];
        }
    }
    __syncthreads();

    // ---- stage C ----
    if (!WRITE) {
        // full-row mapping: thread = (orow, col half); contiguous window
        const int orr = tid & (TILE_H - 1);
        const int h   = tid >> 7;
        const float* w = &s_ut[orr * USTR + 16 * h];

        float win[24];
        #pragma unroll
        for (int j = 0; j < 24; j++) win[j] = w[j];

        float vmin = __int_as_float(0x7f800000);
        float vmax = -vmin;
        #pragma unroll
        for (int n = 0; n < 16; n++) {
            float e = EVEN8(win[n],     win[n + 1], win[n + 2], win[n + 3],
                            win[n + 4], win[n + 5], win[n + 6], win[n + 7]);
            float o = ODD8 (win[n + 1], win[n + 2], win[n + 3], win[n + 4],
                            win[n + 5], win[n + 6], win[n + 7], win[n + 8]);
            vmin = fminf(vmin, fminf(e, o));
            vmax = fmaxf(vmax, fmaxf(e, o));
        }
        #pragma unroll
        for (int m = 16; m; m >>= 1) {
            vmin = fminf(vmin, __shfl_xor_sync(0xffffffffu, vmin, m));
            vmax = fmaxf(vmax, __shfl_xor_sync(0xffffffffu, vmax, m));
        }
        int w5 = tid >> 5, l = tid & 31;
        if (l == 0) { s_red[w5] = vmin; s_red[8 + w5] = vmax; }
        __syncthreads();
        if (tid == 0) {
            float a = s_red[0], b = s_red[8];
            #pragma unroll
            for (int i = 1; i < 8; i++) {
                a = fminf(a, s_red[i]);
                b = fmaxf(b, s_red[8 + i]);
            }
            int slot = blockIdx.y * 16 + blockIdx.x;
            g_pmin[bc * SLOTS + slot] = a;
            g_pmax[bc * SLOTS + slot] = b;
        }
    } else {
        // coalesced mapping: thread = (row, 4-px segment); warp = 2 rows.
        const int seg  = tid & 15;          // 16 segments * 4 px = 64 cols
        const int rsub = tid >> 4;          // 16 rows per iteration
        const int ic0  = 2 * seg;           // window start in s_ut cols
        float* dstb = out + ((size_t)bc * OUT_SZ + blockIdx.y * TILE_H + rsub)
                          * OUT_SZ + blockIdx.x * TILE_W + seg * 4;
        #pragma unroll 2
        for (int it = 0; it < 8; it++) {
            const float* w = &s_ut[(it * 16 + rsub) * USTR + ic0];
            float w0 = w[0], w1 = w[1], w2 = w[2], w3 = w[3], w4 = w[4],
                  w5 = w[5], w6 = w[6], w7 = w[7], w8 = w[8], w9 = w[9];
            float p0 = EVEN8(w0, w1, w2, w3, w4, w5, w6, w7);
            float p1 = ODD8 (w1, w2, w3, w4, w5, w6, w7, w8);
            float p2 = EVEN8(w1, w2, w3, w4, w5, w6, w7, w8);
            float p3 = ODD8 (w2, w3, w4, w5, w6, w7, w8, w9);
            // quantize: trunc(min(P1*v,255)), F2I.U32 clamps negatives to 0
            float f0 = (float)__float2uint_rz(fminf(p0 * P1, 255.0f));
            float f1 = (float)__float2uint_rz(fminf(p1 * P1, 255.0f));
            float f2 = (float)__float2uint_rz(fminf(p2 * P1, 255.0f));
            float f3 = (float)__float2uint_rz(fminf(p3 * P1, 255.0f));
            *reinterpret_cast<float4*>(dstb + (size_t)it * 16 * OUT_SZ) =
                make_float4(f0, f1, f2, f3);
        }
    }
}

extern "C" void kernel_launch(void* const* d_in, const int* in_sizes, int n_in,
                              void* d_out, int out_size)
{
    const float* x = (const float*)d_in[0];
    float* out = (float*)d_out;

    dim3 grid(OUT_SZ / TILE_W, OUT_SZ / TILE_H, NCH);
    k_resize<false><<<grid, 256>>>(x, nullptr);
    k_resize<true ><<<grid, 256>>>(x, out);
}

// round 14
// speedup vs baseline: 1.6069x; 1.4251x over previous
#include <cuda_runtime.h>
#include <cstdint>

// LanczosInterpolationLayer: x f32 [32,3,512,512] -> Lanczos4 2x upsample ->
// per-image range renormalize -> *255 -> uint8 (saturating trunc) -> f32 out.
//
// R13 (187us): P1 is data-independent; min/max only feeds doNorm=(range>1).
// R14: decide doNorm from 1024 EXACT sampled resized values per channel
// (k_sample, ~8us). Full min/max pass early-exits when the sampled range
// is decisively > 1 (sound: samples are true resized outputs); otherwise it
// runs fully and pass-2 uses the exact partials -> correct for ANY input.

#define NIMG   32
#define NCH    96
#define IN_SZ  512
#define OUT_SZ 1024
#define TILE_W 64           // output cols per block
#define TILE_H 128          // output rows per block
#define PAT_W  40           // input patch cols (32 + 8 halo)
#define PAT_H  72           // input patch rows (64 + 8 halo)
#define PSTR   41           // s_in stride (odd -> conflict-free)
#define USTR   41           // s_ut stride [orow][icol] (conflict-free)
#define SLOTS  128          // blocks per channel (16 x * 8 y)

__device__ float g_pmin[NCH * SLOTS];
__device__ float g_pmax[NCH * SLOTS];
__device__ float g_smin[NCH * 4];     // sampled partials (4 blocks/channel)
__device__ float g_smax[NCH * 4];

// Normalized Lanczos4 weights, even phase (output 2m): tap j hits input m-4+j.
#define WE0 (-0.0039706f)
#define WE1 ( 0.0314676f)
#define WE2 (-0.0916620f)
#define WE3 ( 0.2826868f)
#define WE4 ( 0.8933939f)
#define WE5 (-0.1523043f)
#define WE6 ( 0.0554435f)
#define WE7 (-0.0150549f)

#define EVEN8(a0,a1,a2,a3,a4,a5,a6,a7) \
  fmaf((a7), WE7, fmaf((a6), WE6, fmaf((a5), WE5, fmaf((a4), WE4, \
  fmaf((a3), WE3, fmaf((a2), WE2, fmaf((a1), WE1, (a0) * WE0)))))))
#define ODD8(a1,a2,a3,a4,a5,a6,a7,a8) \
  fmaf((a8), WE0, fmaf((a7), WE1, fmaf((a6), WE2, fmaf((a5), WE3, \
  fmaf((a4), WE4, fmaf((a3), WE5, fmaf((a2), WE6, (a1) * WE7)))))))

// ---- sampled decision kernel: exact resized values at (32r',32c') ----
__global__ void __launch_bounds__(256)
k_sample(const float* __restrict__ x)
{
    __shared__ float sm[16];
    const int tid = threadIdx.x;
    const int by  = blockIdx.x;          // 0..3
    const int bc  = blockIdx.z;          // channel
    const int rp  = (by << 3) + (tid >> 5);   // r' 0..31
    const int cp  = tid & 31;                 // c' 0..31
    const int m   = rp << 4;             // input row base (output row 32r')
    const int n   = cp << 4;             // input col base (output col 32c')
    const float* src = x + (size_t)bc * (IN_SZ * IN_SZ);

    float rv[8];
    #pragma unroll
    for (int i = 0; i < 8; i++) {
        int gy = min(max(m - 4 + i, 0), IN_SZ - 1);
        const float* row = src + gy * IN_SZ;
        float a0, a1, a2, a3, a4, a5, a6, a7;
        if (cp == 0) {                    // cols -4..3 clamp to 0
            a0 = a1 = a2 = a3 = a4 = row[0];
            a5 = row[1]; a6 = row[2]; a7 = row[3];
        } else {                          // cols 16c'-4..16c'+3, 16B aligned
            const float4* rr = reinterpret_cast<const float4*>(row + n - 4);
            float4 A = rr[0], B = rr[1];
            a0 = A.x; a1 = A.y; a2 = A.z; a3 = A.w;
            a4 = B.x; a5 = B.y; a6 = B.z; a7 = B.w;
        }
        rv[i] = EVEN8(a0, a1, a2, a3, a4, a5, a6, a7);
    }
    float v = EVEN8(rv[0], rv[1], rv[2], rv[3], rv[4], rv[5], rv[6], rv[7]);

    float a = v, b = v;
    #pragma unroll
    for (int s = 16; s; s >>= 1) {
        a = fminf(a, __shfl_xor_sync(0xffffffffu, a, s));
        b = fmaxf(b, __shfl_xor_sync(0xffffffffu, b, s));
    }
    if ((tid & 31) == 0) { sm[tid >> 5] = a; sm[8 + (tid >> 5)] = b; }
    __syncthreads();
    if (tid == 0) {
        float mn = sm[0], mx = sm[8];
        #pragma unroll
        for (int i = 1; i < 8; i++) {
            mn = fminf(mn, sm[i]);
            mx = fmaxf(mx, sm[8 + i]);
        }
        g_smin[bc * 4 + by] = mn;
        g_smax[bc * 4 + by] = mx;
    }
}

template <bool WRITE>
__global__ void __launch_bounds__(256, 5)
k_resize(const float* __restrict__ x, float* __restrict__ out)
{
    __shared__ float s_in[PAT_H * PSTR];    // input patch  [irow][icol]
    __shared__ float s_ut[TILE_H * USTR];   // H-resampled  [orow][icol]
    __shared__ float s_red[16];
    __shared__ float s_srange;

    const int tid = threadIdx.x;
    const int bc  = blockIdx.z;                  // image*3 + channel
    const int m0  = blockIdx.y * (TILE_H / 2);   // input row base
    const int n0  = blockIdx.x * (TILE_W / 2);   // input col base
    const int img3 = (bc / 3) * 3;
    const float* src = x + (size_t)bc * (IN_SZ * IN_SZ);

    // ---- sampled-range prologue (both passes) ----
    {
        float sa = __int_as_float(0x7f800000);
        float sb = -sa;
        if (tid < 12) {                   // 3 channels * 4 slots, contiguous
            sa = g_smin[img3 * 4 + tid];
            sb = g_smax[img3 * 4 + tid];
        }
        if (tid < 32) {
            #pragma unroll
            for (int s = 16; s; s >>= 1) {
                sa = fminf(sa, __shfl_xor_sync(0xffffffffu, sa, s));
                sb = fmaxf(sb, __shfl_xor_sync(0xffffffffu, sb, s));
            }
            if (tid == 0) s_srange = sb - sa;
        }
    }

    if (!WRITE) {
        __syncthreads();
        if (s_srange > 1.001f) return;    // decided: doNorm true, skip exact
    }

    // ---- pass 2 only: reduce this image's 384 exact min/max partials ----
    // (values used only when the sampled range did NOT decide; in that case
    //  pass 1 ran fully and the partials are valid.)
    if (WRITE) {
        float a = __int_as_float(0x7f800000);
        float b = -a;
        #pragma unroll
        for (int i = 0; i < 2; i++) {
            int idx = tid + 256 * i;
            if (idx < 3 * SLOTS) {
                a = fminf(a, g_pmin[img3 * SLOTS + idx]);
                b = fmaxf(b, g_pmax[img3 * SLOTS + idx]);
            }
        }
        #pragma unroll
        for (int m = 16; m; m >>= 1) {
            a = fminf(a, __shfl_xor_sync(0xffffffffu, a, m));
            b = fmaxf(b, __shfl_xor_sync(0xffffffffu, b, m));
        }
        if ((tid & 31) == 0) {
            s_red[tid >> 5]       = a;
            s_red[8 + (tid >> 5)] = b;
        }
    }

    // ---- stage A: load input patch with replicate border ----
    #pragma unroll
    for (int i = 0; i < 12; i++) {
        int idx = tid + 256 * i;
        if (idx < PAT_H * PAT_W) {
            int r = idx / PAT_W;
            int c = idx - r * PAT_W;
            int gy = min(max(m0 - 4 + r, 0), IN_SZ - 1);
            int gx = min(max(n0 - 4 + c, 0), IN_SZ - 1);
            s_in[r * PSTR + c] = src[gy * IN_SZ + gx];
        }
    }
    __syncthreads();

    // epilogue constant: f = clamp(trunc(min(P1*v, 255)), 0, 255)
    float P1 = 255.0f;
    if (WRITE) {
        bool doNorm;
        if (s_srange > 1.001f) {
            doNorm = true;                 // decided by exact sampled values
        } else {
            float mn = s_red[0], mx = s_red[8];
            #pragma unroll
            for (int i = 1; i < 8; i++) {
                mn = fminf(mn, s_red[i]);
                mx = fmaxf(mx, s_red[8 + i]);
            }
            doNorm = (mx - mn) > 1.0f;
        }
        if (doNorm) {
            const float c1 = 1.0f - 1.0f / 255.0f;     // 254/255
            const float c2 = 1.0f + 10.0f / 255.0f;    // 265/255
            P1 = 255.0f * c1 * c2;                      // 263.9608
        }
    }

    // ---- stage B: vertical (height) resample -> s_ut[orow][icol] ----
    for (int t = tid; t < PAT_W * 8; t += 256) {
        int g  = t / PAT_W;
        int ic = t - g * PAT_W;
        int mb = g * 8;
        const float* p = &s_in[mb * PSTR + ic];
        float w0 = p[0 * PSTR], w1 = p[1 * PSTR], w2 = p[2 * PSTR];
        float w3 = p[3 * PSTR], w4 = p[4 * PSTR], w5 = p[5 * PSTR];
        float w6 = p[6 * PSTR], w7 = p[7 * PSTR], w8 = p[8 * PSTR];
        float* q = &s_ut[2 * mb * USTR + ic];
        #pragma unroll
        for (int mm = 0; mm < 8; mm++) {
            q[(2 * mm)     * USTR] = EVEN8(w0, w1, w2, w3, w4, w5, w6, w7);
            q[(2 * mm + 1) * USTR] = ODD8(w1, w2, w3, w4, w5, w6, w7, w8);
            w0 = w1; w1 = w2; w2 = w3; w3 = w4;
            w4 = w5; w5 = w6; w6 = w7; w7 = w8;
            if (mm < 7) w8 = p[(mm + 9) * PSTR];
        }
    }
    __syncthreads();

    // ---- stage C ----
    if (!WRITE) {
        const int orr = tid & (TILE_H - 1);
        const int h   = tid >> 7;
        const float* w = &s_ut[orr * USTR + 16 * h];

        float win[24];
        #pragma unroll
        for (int j = 0; j < 24; j++) win[j] = w[j];

        float vmin = __int_as_float(0x7f800000);
        float vmax = -vmin;
        #pragma unroll
        for (int n = 0; n < 16; n++) {
            float e = EVEN8(win[n],     win[n + 1], win[n + 2], win[n + 3],
                            win[n + 4], win[n + 5], win[n + 6], win[n + 7]);
            float o = ODD8 (win[n + 1], win[n + 2], win[n + 3], win[n + 4],
                            win[n + 5], win[n + 6], win[n + 7], win[n + 8]);
            vmin = fminf(vmin, fminf(e, o));
            vmax = fmaxf(vmax, fmaxf(e, o));
        }
        #pragma unroll
        for (int m = 16; m; m >>= 1) {
            vmin = fminf(vmin, __shfl_xor_sync(0xffffffffu, vmin, m));
            vmax = fmaxf(vmax, __shfl_xor_sync(0xffffffffu, vmax, m));
        }
        int w5 = tid >> 5, l = tid & 31;
        if (l == 0) { s_red[w5] = vmin; s_red[8 + w5] = vmax; }
        __syncthreads();
        if (tid == 0) {
            float a = s_red[0], b = s_red[8];
            #pragma unroll
            for (int i = 1; i < 8; i++) {
                a = fminf(a, s_red[i]);
                b = fmaxf(b, s_red[8 + i]);
            }
            int slot = blockIdx.y * 16 + blockIdx.x;
            g_pmin[bc * SLOTS + slot] = a;
            g_pmax[bc * SLOTS + slot] = b;
        }
    } else {
        const int seg  = tid & 15;
        const int rsub = tid >> 4;
        const int ic0  = 2 * seg;
        float* dstb = out + ((size_t)bc * OUT_SZ + blockIdx.y * TILE_H + rsub)
                          * OUT_SZ + blockIdx.x * TILE_W + seg * 4;
        #pragma unroll 2
        for (int it = 0; it < 8; it++) {
            const float* w = &s_ut[(it * 16 + rsub) * USTR + ic0];
            float w0 = w[0], w1 = w[1], w2 = w[2], w3 = w[3], w4 = w[4],
                  w5 = w[5], w6 = w[6], w7 = w[7], w8 = w[8], w9 = w[9];
            float p0 = EVEN8(w0, w1, w2, w3, w4, w5, w6, w7);
            float p1 = ODD8 (w1, w2, w3, w4, w5, w6, w7, w8);
            float p2 = EVEN8(w1, w2, w3, w4, w5, w6, w7, w8);
            float p3 = ODD8 (w2, w3, w4, w5, w6, w7, w8, w9);
            float f0 = (float)__float2uint_rz(fminf(p0 * P1, 255.0f));
            float f1 = (float)__float2uint_rz(fminf(p1 * P1, 255.0f));
            float f2 = (float)__float2uint_rz(fminf(p2 * P1, 255.0f));
            float f3 = (float)__float2uint_rz(fminf(p3 * P1, 255.0f));
            *reinterpret_cast<float4*>(dstb + (size_t)it * 16 * OUT_SZ) =
                make_float4(f0, f1, f2, f3);
        }
    }
}

extern "C" void kernel_launch(void* const* d_in, const int* in_sizes, int n_in,
                              void* d_out, int out_size)
{
    const float* x = (const float*)d_in[0];
    float* out = (float*)d_out;

    k_sample<<<dim3(4, 1, NCH), 256>>>(x);
    dim3 grid(OUT_SZ / TILE_W, OUT_SZ / TILE_H, NCH);
    k_resize<false><<<grid, 256>>>(x, nullptr);
    k_resize<true ><<<grid, 256>>>(x, out);
}

// round 15
// speedup vs baseline: 1.7111x; 1.0649x over previous
#include <cuda_runtime.h>
#include <cstdint>

// LanczosInterpolationLayer: x f32 [32,3,512,512] -> Lanczos4 2x upsample ->
// per-image range renormalize -> *255 -> uint8 (saturating trunc) -> f32 out.
//
// R14 (131.3us) = sampled doNorm decision + early-exit exact pass + pass-2.
// R15 shrinks decision overhead:
//  - k_sample: one block per IMAGE (grid 32; 16x16 samples/ch at stride 64,
//    3 channels/thread), reduces in-block, writes ONE float g_srange[img].
//  - both passes: prologue = single broadcast load of g_srange (no per-block
//    12-wide reduce); pass-2 skips the 384-partial reduce when decided.
//  - exact fallback path retained verbatim (correct for ANY input).

#define NIMG   32
#define NCH    96
#define IN_SZ  512
#define OUT_SZ 1024
#define TILE_W 64           // output cols per block
#define TILE_H 128          // output rows per block
#define PAT_W  40           // input patch cols (32 + 8 halo)
#define PAT_H  72           // input patch rows (64 + 8 halo)
#define PSTR   41           // s_in stride (odd -> conflict-free)
#define USTR   41           // s_ut stride [orow][icol] (conflict-free)
#define SLOTS  128          // blocks per channel (16 x * 8 y)

__device__ float g_pmin[NCH * SLOTS];
__device__ float g_pmax[NCH * SLOTS];
__device__ float g_srange[NIMG];      // sampled range per image (no init)

// Normalized Lanczos4 weights, even phase (output 2m): tap j hits input m-4+j.
#define WE0 (-0.0039706f)
#define WE1 ( 0.0314676f)
#define WE2 (-0.0916620f)
#define WE3 ( 0.2826868f)
#define WE4 ( 0.8933939f)
#define WE5 (-0.1523043f)
#define WE6 ( 0.0554435f)
#define WE7 (-0.0150549f)

#define EVEN8(a0,a1,a2,a3,a4,a5,a6,a7) \
  fmaf((a7), WE7, fmaf((a6), WE6, fmaf((a5), WE5, fmaf((a4), WE4, \
  fmaf((a3), WE3, fmaf((a2), WE2, fmaf((a1), WE1, (a0) * WE0)))))))
#define ODD8(a1,a2,a3,a4,a5,a6,a7,a8) \
  fmaf((a8), WE0, fmaf((a7), WE1, fmaf((a6), WE2, fmaf((a5), WE3, \
  fmaf((a4), WE4, fmaf((a3), WE5, fmaf((a2), WE6, (a1) * WE7)))))))

// ---- sampled decision: 16x16 exact resized values per channel, 1 blk/img ----
__global__ void __launch_bounds__(256)
k_sample(const float* __restrict__ x)
{
    __shared__ float sm[16];
    const int tid = threadIdx.x;
    const int img = blockIdx.x;
    const int rp  = tid >> 4;            // 0..15
    const int cp  = tid & 15;            // 0..15
    const int m   = rp << 5;             // input row base (output row 64r')
    const int n   = cp << 5;             // input col base (output col 64c')

    float vmin = __int_as_float(0x7f800000);
    float vmax = -vmin;

    #pragma unroll
    for (int ch = 0; ch < 3; ch++) {
        const float* src = x + (size_t)(img * 3 + ch) * (IN_SZ * IN_SZ);
        float rv[8];
        #pragma unroll
        for (int i = 0; i < 8; i++) {
            int gy = min(max(m - 4 + i, 0), IN_SZ - 1);
            const float* row = src + gy * IN_SZ;
            float a0, a1, a2, a3, a4, a5, a6, a7;
            if (cp == 0) {                // cols -4..3 clamp to 0
                a0 = a1 = a2 = a3 = a4 = row[0];
                a5 = row[1]; a6 = row[2]; a7 = row[3];
            } else {                      // cols n-4..n+3, 16B aligned
                const float4* rr = reinterpret_cast<const float4*>(row + n - 4);
                float4 A = rr[0], B = rr[1];
                a0 = A.x; a1 = A.y; a2 = A.z; a3 = A.w;
                a4 = B.x; a5 = B.y; a6 = B.z; a7 = B.w;
            }
            rv[i] = EVEN8(a0, a1, a2, a3, a4, a5, a6, a7);
        }
        float v = EVEN8(rv[0], rv[1], rv[2], rv[3], rv[4], rv[5], rv[6], rv[7]);
        vmin = fminf(vmin, v);
        vmax = fmaxf(vmax, v);
    }

    #pragma unroll
    for (int s = 16; s; s >>= 1) {
        vmin = fminf(vmin, __shfl_xor_sync(0xffffffffu, vmin, s));
        vmax = fmaxf(vmax, __shfl_xor_sync(0xffffffffu, vmax, s));
    }
    if ((tid & 31) == 0) { sm[tid >> 5] = vmin; sm[8 + (tid >> 5)] = vmax; }
    __syncthreads();
    if (tid == 0) {
        float mn = sm[0], mx = sm[8];
        #pragma unroll
        for (int i = 1; i < 8; i++) {
            mn = fminf(mn, sm[i]);
            mx = fmaxf(mx, sm[8 + i]);
        }
        g_srange[img] = mx - mn;
    }
}

template <bool WRITE>
__global__ void __launch_bounds__(256, 5)
k_resize(const float* __restrict__ x, float* __restrict__ out)
{
    __shared__ float s_in[PAT_H * PSTR];    // input patch  [irow][icol]
    __shared__ float s_ut[TILE_H * USTR];   // H-resampled  [orow][icol]
    __shared__ float s_red[16];
    __shared__ float s_srange;

    const int tid = threadIdx.x;
    const int bc  = blockIdx.z;                  // image*3 + channel
    const int m0  = blockIdx.y * (TILE_H / 2);   // input row base
    const int n0  = blockIdx.x * (TILE_W / 2);   // input col base
    const int img = bc / 3;
    const float* src = x + (size_t)bc * (IN_SZ * IN_SZ);

    // ---- prologue: one broadcast load of the sampled range ----
    if (tid == 0) s_srange = g_srange[img];
    __syncthreads();
    const bool decided = s_srange > 1.001f;

    if (!WRITE && decided) return;      // doNorm certain; skip exact pass

    // ---- pass 2, undecided only: reduce 384 exact min/max partials ----
    if (WRITE && !decided) {
        const int img3 = img * 3;
        float a = __int_as_float(0x7f800000);
        float b = -a;
        #pragma unroll
        for (int i = 0; i < 2; i++) {
            int idx = tid + 256 * i;
            if (idx < 3 * SLOTS) {
                a = fminf(a, g_pmin[img3 * SLOTS + idx]);
                b = fmaxf(b, g_pmax[img3 * SLOTS + idx]);
            }
        }
        #pragma unroll
        for (int m = 16; m; m >>= 1) {
            a = fminf(a, __shfl_xor_sync(0xffffffffu, a, m));
            b = fmaxf(b, __shfl_xor_sync(0xffffffffu, b, m));
        }
        if ((tid & 31) == 0) {
            s_red[tid >> 5]       = a;
            s_red[8 + (tid >> 5)] = b;
        }
    }

    // ---- stage A: load input patch with replicate border ----
    #pragma unroll
    for (int i = 0; i < 12; i++) {
        int idx = tid + 256 * i;
        if (idx < PAT_H * PAT_W) {
            int r = idx / PAT_W;
            int c = idx - r * PAT_W;
            int gy = min(max(m0 - 4 + r, 0), IN_SZ - 1);
            int gx = min(max(n0 - 4 + c, 0), IN_SZ - 1);
            s_in[r * PSTR + c] = src[gy * IN_SZ + gx];
        }
    }
    __syncthreads();

    // epilogue constant: f = clamp(trunc(min(P1*v, 255)), 0, 255)
    float P1 = 255.0f;
    if (WRITE) {
        bool doNorm = true;
        if (!decided) {
            float mn = s_red[0], mx = s_red[8];
            #pragma unroll
            for (int i = 1; i < 8; i++) {
                mn = fminf(mn, s_red[i]);
                mx = fmaxf(mx, s_red[8 + i]);
            }
            doNorm = (mx - mn) > 1.0f;
        }
        if (doNorm) {
            const float c1 = 1.0f - 1.0f / 255.0f;     // 254/255
            const float c2 = 1.0f + 10.0f / 255.0f;    // 265/255
            P1 = 255.0f * c1 * c2;                      // 263.9608
        }
    }

    // ---- stage B: vertical (height) resample -> s_ut[orow][icol] ----
    for (int t = tid; t < PAT_W * 8; t += 256) {
        int g  = t / PAT_W;
        int ic = t - g * PAT_W;
        int mb = g * 8;
        const float* p = &s_in[mb * PSTR + ic];
        float w0 = p[0 * PSTR], w1 = p[1 * PSTR], w2 = p[2 * PSTR];
        float w3 = p[3 * PSTR], w4 = p[4 * PSTR], w5 = p[5 * PSTR];
        float w6 = p[6 * PSTR], w7 = p[7 * PSTR], w8 = p[8 * PSTR];
        float* q = &s_ut[2 * mb * USTR + ic];
        #pragma unroll
        for (int mm = 0; mm < 8; mm++) {
            q[(2 * mm)     * USTR] = EVEN8(w0, w1, w2, w3, w4, w5, w6, w7);
            q[(2 * mm + 1) * USTR] = ODD8(w1, w2, w3, w4, w5, w6, w7, w8);
            w0 = w1; w1 = w2; w2 = w3; w3 = w4;
            w4 = w5; w5 = w6; w6 = w7; w7 = w8;
            if (mm < 7) w8 = p[(mm + 9) * PSTR];
        }
    }
    __syncthreads();

    // ---- stage C ----
    if (!WRITE) {
        const int orr = tid & (TILE_H - 1);
        const int h   = tid >> 7;
        const float* w = &s_ut[orr * USTR + 16 * h];

        float win[24];
        #pragma unroll
        for (int j = 0; j < 24; j++) win[j] = w[j];

        float vmin = __int_as_float(0x7f800000);
        float vmax = -vmin;
        #pragma unroll
        for (int n = 0; n < 16; n++) {
            float e = EVEN8(win[n],     win[n + 1], win[n + 2], win[n + 3],
                            win[n + 4], win[n + 5], win[n + 6], win[n + 7]);
            float o = ODD8 (win[n + 1], win[n + 2], win[n + 3], win[n + 4],
                            win[n + 5], win[n + 6], win[n + 7], win[n + 8]);
            vmin = fminf(vmin, fminf(e, o));
            vmax = fmaxf(vmax, fmaxf(e, o));
        }
        #pragma unroll
        for (int m = 16; m; m >>= 1) {
            vmin = fminf(vmin, __shfl_xor_sync(0xffffffffu, vmin, m));
            vmax = fmaxf(vmax, __shfl_xor_sync(0xffffffffu, vmax, m));
        }
        int w5 = tid >> 5, l = tid & 31;
        if (l == 0) { s_red[w5] = vmin; s_red[8 + w5] = vmax; }
        __syncthreads();
        if (tid == 0) {
            float a = s_red[0], b = s_red[8];
            #pragma unroll
            for (int i = 1; i < 8; i++) {
                a = fminf(a, s_red[i]);
                b = fmaxf(b, s_red[8 + i]);
            }
            int slot = blockIdx.y * 16 + blockIdx.x;
            g_pmin[bc * SLOTS + slot] = a;
            g_pmax[bc * SLOTS + slot] = b;
        }
    } else {
        const int seg  = tid & 15;
        const int rsub = tid >> 4;
        const int ic0  = 2 * seg;
        float* dstb = out + ((size_t)bc * OUT_SZ + blockIdx.y * TILE_H + rsub)
                          * OUT_SZ + blockIdx.x * TILE_W + seg * 4;
        #pragma unroll 2
        for (int it = 0; it < 8; it++) {
            const float* w = &s_ut[(it * 16 + rsub) * USTR + ic0];
            float w0 = w[0], w1 = w[1], w2 = w[2], w3 = w[3], w4 = w[4],
                  w5 = w[5], w6 = w[6], w7 = w[7], w8 = w[8], w9 = w[9];
            float p0 = EVEN8(w0, w1, w2, w3, w4, w5, w6, w7);
            float p1 = ODD8 (w1, w2, w3, w4, w5, w6, w7, w8);
            float p2 = EVEN8(w1, w2, w3, w4, w5, w6, w7, w8);
            float p3 = ODD8 (w2, w3, w4, w5, w6, w7, w8, w9);
            float f0 = (float)__float2uint_rz(fminf(p0 * P1, 255.0f));
            float f1 = (float)__float2uint_rz(fminf(p1 * P1, 255.0f));
            float f2 = (float)__float2uint_rz(fminf(p2 * P1, 255.0f));
            float f3 = (float)__float2uint_rz(fminf(p3 * P1, 255.0f));
            *reinterpret_cast<float4*>(dstb + (size_t)it * 16 * OUT_SZ) =
                make_float4(f0, f1, f2, f3);
        }
    }
}

extern "C" void kernel_launch(void* const* d_in, const int* in_sizes, int n_in,
                              void* d_out, int out_size)
{
    const float* x = (const float*)d_in[0];
    float* out = (float*)d_out;

    k_sample<<<NIMG, 256>>>(x);
    dim3 grid(OUT_SZ / TILE_W, OUT_SZ / TILE_H, NCH);
    k_resize<false><<<grid, 256>>>(x, nullptr);
    k_resize<true ><<<grid, 256>>>(x, out);
}